// round 8
// baseline (speedup 1.0000x reference)
#include <cuda_runtime.h>
#include <cstdint>

#define B_SZ   32
#define N_E    500000
#define N_T    2000000
#define N_R    200
#define N_W2V  300
#define CAP    32        // max triples per object entity (λ=4 Poisson; P(>32) ~ 0)

// Entity-major buffers [N_E][32]; buf0 = T(x), buf_k = result after hop k.
__device__ float g_buf0[(size_t)N_E * B_SZ];
__device__ float g_buf1[(size_t)N_E * B_SZ];
__device__ float g_buf2[(size_t)N_E * B_SZ];
__device__ float g_buf3[(size_t)N_E * B_SZ];
__device__ float g_rt[3 * N_R * B_SZ];

// Binning structures. g_cnt is zero-initialized at module load and re-zeroed
// at the END of every call (in the transpose_out launch), preserving the
// "cnt == 0 on entry" invariant across graph replays.
__device__ int  g_cnt[N_E];
__device__ int2 g_pairs[(size_t)N_E * CAP];   // (subj, rel) per slot

// ---------------------------------------------------------------------------
// Fused prologue, one launch, 256-thread blocks, dispatch on blockIdx.x:
//   [0, FILL)              : bin triples by obj into g_pairs / g_cnt
//   [FILL, FILL+TIN)       : transpose x [32,N_E] -> buf0 [N_E,32]
//   [FILL+TIN, +RMLP)      : rt[hop][rel][batch] = (q @ W_hop + b_hop)^T
// Sections touch disjoint memory; no intra-launch ordering needed.
// ---------------------------------------------------------------------------
#define PRE_FILL_BLOCKS 7813    // ceil(2,000,000 / 256)
#define PRE_TIN_BLOCKS  15625   // 500,000 / 32
#define PRE_RMLP_BLOCKS 75      // 600 warps / 8
#define PRE_TOTAL_BLOCKS (PRE_FILL_BLOCKS + PRE_TIN_BLOCKS + PRE_RMLP_BLOCKS)

__global__ void __launch_bounds__(256)
fused_pre_kernel(const float* __restrict__ x, const float* __restrict__ q,
                 const int* __restrict__ subj, const int* __restrict__ rel,
                 const int* __restrict__ obj,
                 const float* __restrict__ W1, const float* __restrict__ b1,
                 const float* __restrict__ W2, const float* __restrict__ b2,
                 const float* __restrict__ W3, const float* __restrict__ b3,
                 float* __restrict__ buf0, float* __restrict__ rt) {
    int bid = blockIdx.x;
    int tid = threadIdx.x;

    if (bid < PRE_FILL_BLOCKS) {
        // ---- fill section: one thread per triple ----
        int t = bid * 256 + tid;
        if (t < N_T) {
            int o = __ldg(obj + t);
            int slot = atomicAdd(&g_cnt[o], 1);
            if (slot < CAP) {
                g_pairs[(size_t)o * CAP + slot] =
                    make_int2(__ldg(subj + t), __ldg(rel + t));
            }
        }
        return;
    }

    if (bid < PRE_FILL_BLOCKS + PRE_TIN_BLOCKS) {
        // ---- transpose-in section: 32 entities per block ----
        __shared__ float tile[32][33];
        int e0 = (bid - PRE_FILL_BLOCKS) * 32;
        int tx = tid & 31;
        int row = tid >> 5;       // 0..7
#pragma unroll
        for (int p = 0; p < 4; p++) {
            int b = row + p * 8;
            tile[b][tx] = x[(size_t)b * N_E + e0 + tx];
        }
        __syncthreads();
#pragma unroll
        for (int p = 0; p < 4; p++) {
            int j = row + p * 8;
            buf0[(size_t)(e0 + j) * 32 + tx] = tile[tx][j];
        }
        return;
    }

    // ---- rmlp section: 8 (hop,rel) warps per block ----
    {
        int gw   = (bid - PRE_FILL_BLOCKS - PRE_TIN_BLOCKS) * 8 + (tid >> 5);
        int lane = tid & 31;
        int hop  = gw / N_R;
        int rel_i = gw - hop * N_R;

        const float* W = (hop == 0) ? W1 : (hop == 1) ? W2 : W3;
        const float* b = (hop == 0) ? b1 : (hop == 1) ? b2 : b3;

        float acc = b[rel_i];
        const float* qrow = q + (size_t)lane * N_W2V;
#pragma unroll 4
        for (int k = 0; k < N_W2V; k++) {
            acc += qrow[k] * W[(size_t)k * N_R + rel_i];
        }
        rt[((size_t)hop * N_R + rel_i) * B_SZ + lane] = acc;
    }
}

// ---------------------------------------------------------------------------
// One hop, segmented: warp per object entity e.
//   dst[e][:] = sum over triples (s,r) in bucket e of src[s][:] * rt[r][:]
// Lane = batch. Pairs loaded coalesced (lane i -> slot i), indices broadcast
// via shfl, gathers issued 4-wide for MLP. dst written once: full 128B line,
// no atomics, no zero-init required (every entity overwritten).
// ---------------------------------------------------------------------------
__global__ void __launch_bounds__(256)
hop_kernel(const float* __restrict__ src, float* __restrict__ dst,
           const float* __restrict__ rt,
           const int* __restrict__ n_hop, int hop) {
    if (*n_hop < hop) return;

    int tid  = threadIdx.x;
    int lane = tid & 31;
    int e    = blockIdx.x * 8 + (tid >> 5);       // 8 warps/block, warp = entity
    if (e >= N_E) return;

    int n = __ldg(&g_cnt[e]);
    n = n > CAP ? CAP : n;

    int2 p = make_int2(0, 0);
    if (lane < n) p = g_pairs[(size_t)e * CAP + lane];

    float acc = 0.f;
    int i = 0;
    for (; i + 4 <= n; i += 4) {
        int s0 = __shfl_sync(0xffffffffu, p.x, i + 0);
        int r0 = __shfl_sync(0xffffffffu, p.y, i + 0);
        int s1 = __shfl_sync(0xffffffffu, p.x, i + 1);
        int r1 = __shfl_sync(0xffffffffu, p.y, i + 1);
        int s2 = __shfl_sync(0xffffffffu, p.x, i + 2);
        int r2 = __shfl_sync(0xffffffffu, p.y, i + 2);
        int s3 = __shfl_sync(0xffffffffu, p.x, i + 3);
        int r3 = __shfl_sync(0xffffffffu, p.y, i + 3);
        // front-batch the 4 long-latency gathers
        float a0 = __ldg(src + (size_t)s0 * 32 + lane);
        float a1 = __ldg(src + (size_t)s1 * 32 + lane);
        float a2 = __ldg(src + (size_t)s2 * 32 + lane);
        float a3 = __ldg(src + (size_t)s3 * 32 + lane);
        float w0 = __ldg(rt + (size_t)r0 * 32 + lane);
        float w1 = __ldg(rt + (size_t)r1 * 32 + lane);
        float w2 = __ldg(rt + (size_t)r2 * 32 + lane);
        float w3 = __ldg(rt + (size_t)r3 * 32 + lane);
        acc = fmaf(a0, w0, acc);
        acc = fmaf(a1, w1, acc);
        acc = fmaf(a2, w2, acc);
        acc = fmaf(a3, w3, acc);
    }
    for (; i < n; i++) {
        int s = __shfl_sync(0xffffffffu, p.x, i);
        int r = __shfl_sync(0xffffffffu, p.y, i);
        acc = fmaf(__ldg(src + (size_t)s * 32 + lane),
                   __ldg(rt + (size_t)r * 32 + lane), acc);
    }

    dst[(size_t)e * 32 + lane] = acc;
}

// ---------------------------------------------------------------------------
// Epilogue, one launch (1024-thread blocks):
//   [0, 15625)      : transpose selected buffer [N_E,32] -> out [32,N_E]
//   [15625, 16114)  : zero g_cnt for the next call (hop3 already consumed it)
// ---------------------------------------------------------------------------
#define TOUT_BLOCKS 15625
#define CNTZ_BLOCKS 489    // ceil(500000 / 1024)

__global__ void transpose_out_kernel(const float* __restrict__ b0,
                                     const float* __restrict__ b1,
                                     const float* __restrict__ b2,
                                     const float* __restrict__ b3,
                                     const int* __restrict__ n_hop,
                                     float* __restrict__ out) {
    int bid = blockIdx.x;
    int tx = threadIdx.x, ty = threadIdx.y;

    if (bid >= TOUT_BLOCKS) {
        int idx = (bid - TOUT_BLOCKS) * 1024 + ty * 32 + tx;
        if (idx < N_E) g_cnt[idx] = 0;
        return;
    }

    __shared__ float tile[32][33];
    int nh = *n_hop;
    nh = nh < 0 ? 0 : (nh > 3 ? 3 : nh);
    const float* wt = (nh == 0) ? b0 : (nh == 1) ? b1 : (nh == 2) ? b2 : b3;

    int e0 = bid * 32;
    tile[ty][tx] = wt[(size_t)(e0 + ty) * 32 + tx];
    __syncthreads();
    out[(size_t)ty * N_E + e0 + tx] = tile[tx][ty];
}

// ---------------------------------------------------------------------------
// kernel_launch
// Input order (metadata): x, q, subj_idx, rel_idx, obj_idx, W1, b1, W2, b2, W3, b3, n_hop
// ---------------------------------------------------------------------------
extern "C" void kernel_launch(void* const* d_in, const int* in_sizes, int n_in,
                              void* d_out, int out_size) {
    const float* x     = (const float*)d_in[0];
    const float* q     = (const float*)d_in[1];
    const int* subj    = (const int*)d_in[2];
    const int* rel     = (const int*)d_in[3];
    const int* obj     = (const int*)d_in[4];
    const float* W1    = (const float*)d_in[5];
    const float* b1    = (const float*)d_in[6];
    const float* W2    = (const float*)d_in[7];
    const float* b2    = (const float*)d_in[8];
    const float* W3    = (const float*)d_in[9];
    const float* b3    = (const float*)d_in[10];
    const int* n_hop   = (const int*)d_in[11];
    float* out         = (float*)d_out;

    float *buf0, *buf1, *buf2, *buf3, *rt;
    cudaGetSymbolAddress((void**)&buf0, g_buf0);
    cudaGetSymbolAddress((void**)&buf1, g_buf1);
    cudaGetSymbolAddress((void**)&buf2, g_buf2);
    cudaGetSymbolAddress((void**)&buf3, g_buf3);
    cudaGetSymbolAddress((void**)&rt, g_rt);

    // prologue: bin triples + transpose-in + rmlp, one launch
    // (g_cnt is zero on entry: zero-init at load, re-zeroed at end of each call)
    fused_pre_kernel<<<PRE_TOTAL_BLOCKS, 256>>>(
        x, q, subj, rel, obj, W1, b1, W2, b2, W3, b3, buf0, rt);

    // hops: warp per entity, segmented reduction, no atomics, no zeroing
    const int HOP_BLOCKS = N_E / 8;   // 62500 (8 warps/block, exact)
    hop_kernel<<<HOP_BLOCKS, 256>>>(buf0, buf1, rt + 0 * N_R * B_SZ, n_hop, 1);
    hop_kernel<<<HOP_BLOCKS, 256>>>(buf1, buf2, rt + 1 * N_R * B_SZ, n_hop, 2);
    hop_kernel<<<HOP_BLOCKS, 256>>>(buf2, buf3, rt + 2 * N_R * B_SZ, n_hop, 3);

    // epilogue: transpose selected buffer to [B, N_E] + reset g_cnt
    transpose_out_kernel<<<TOUT_BLOCKS + CNTZ_BLOCKS, dim3(32, 32)>>>(
        buf0, buf1, buf2, buf3, n_hop, out);
}

// round 9
// speedup vs baseline: 1.9881x; 1.9881x over previous
#include <cuda_runtime.h>
#include <cstdint>

#define B_SZ   32
#define N_E    500000
#define N_T    2000000
#define N_R    200
#define N_W2V  300

// Scratch: entity-major buffers [N_E][32] (buf0 = T(x), buf_k = result after hop k)
// and r activations [3][N_R][32]
__device__ float g_buf0[(size_t)N_E * B_SZ];
__device__ float g_buf1[(size_t)N_E * B_SZ];
__device__ float g_buf2[(size_t)N_E * B_SZ];
__device__ float g_buf3[(size_t)N_E * B_SZ];
__device__ float g_rt[3 * N_R * B_SZ];

#define ZERO_BLOCKS 15625   // 4M float4 / 256 threads

// ---------------------------------------------------------------------------
// Fused prologue, one launch, 256-thread blocks, dispatch on blockIdx.x:
//   [0, 300)           : rmlp — 2 (hop,rel) tasks per block, 4 warps per task
//                        (k-loop split 75/warp, smem-reduced). FIRST so the
//                        serial-latency work starts in wave 0, not the tail.
//   [300, 300+15625)   : zero buf1 (hop1's destination)
//   [.., +15625)       : transpose x [32,N_E] -> buf0 [N_E,32]
// Sections touch disjoint memory; no intra-launch ordering needed.
// ---------------------------------------------------------------------------
#define PRE_RMLP_BLOCKS 300     // 600 tasks / 2 per block
#define PRE_TIN_BLOCKS  15625
#define PRE_TOTAL_BLOCKS (PRE_RMLP_BLOCKS + ZERO_BLOCKS + PRE_TIN_BLOCKS)

__global__ void __launch_bounds__(256)
fused_pre_kernel(const float* __restrict__ x, const float* __restrict__ q,
                 const float* __restrict__ W1, const float* __restrict__ b1,
                 const float* __restrict__ W2, const float* __restrict__ b2,
                 const float* __restrict__ W3, const float* __restrict__ b3,
                 float* __restrict__ buf0, float4* __restrict__ z1,
                 float* __restrict__ rt) {
    int bid = blockIdx.x;
    int tid = threadIdx.x;

    if (bid < PRE_RMLP_BLOCKS) {
        // ---- rmlp section ----
        __shared__ float partial[2][4][32];
        int task   = tid >> 7;            // 0..1 within block
        int wg_tid = tid & 127;
        int wip    = wg_tid >> 5;         // warp in task: 0..3
        int lane   = tid & 31;            // batch
        int gt     = bid * 2 + task;      // global (hop,rel) task: 0..599
        int hop    = gt / N_R;
        int rel    = gt - hop * N_R;

        const float* W = (hop == 0) ? W1 : (hop == 1) ? W2 : W3;
        const float* b = (hop == 0) ? b1 : (hop == 1) ? b2 : b3;

        // each warp covers k in [wip*75, wip*75+75)
        int k0 = wip * 75;
        const float* qrow = q + (size_t)lane * N_W2V;
        float a0 = 0.f, a1 = 0.f, a2 = 0.f;
#pragma unroll
        for (int k = 0; k < 75; k += 3) {
            a0 = fmaf(qrow[k0 + k + 0], __ldg(W + (size_t)(k0 + k + 0) * N_R + rel), a0);
            a1 = fmaf(qrow[k0 + k + 1], __ldg(W + (size_t)(k0 + k + 1) * N_R + rel), a1);
            a2 = fmaf(qrow[k0 + k + 2], __ldg(W + (size_t)(k0 + k + 2) * N_R + rel), a2);
        }
        partial[task][wip][lane] = a0 + a1 + a2;
        __syncthreads();

        if (wg_tid < 32) {
            float acc = b[rel] + partial[task][0][lane] + partial[task][1][lane]
                      + partial[task][2][lane] + partial[task][3][lane];
            rt[((size_t)hop * N_R + rel) * B_SZ + lane] = acc;
        }
        return;
    }

    if (bid < PRE_RMLP_BLOCKS + ZERO_BLOCKS) {
        size_t i = (size_t)(bid - PRE_RMLP_BLOCKS) * 256 + tid;
        z1[i] = make_float4(0.f, 0.f, 0.f, 0.f);
        return;
    }

    // ---- transpose-in section: 32 entities per block ----
    {
        __shared__ float tile[32][33];
        int e0 = (bid - PRE_RMLP_BLOCKS - ZERO_BLOCKS) * 32;
        int tx = tid & 31;
        int row = tid >> 5;       // 0..7
#pragma unroll
        for (int p = 0; p < 4; p++) {
            int b = row + p * 8;
            tile[b][tx] = x[(size_t)b * N_E + e0 + tx];
        }
        __syncthreads();
#pragma unroll
        for (int p = 0; p < 4; p++) {
            int j = row + p * 8;
            buf0[(size_t)(e0 + j) * 32 + tx] = tile[tx][j];
        }
    }
}

// ---------------------------------------------------------------------------
// Transpose selected buffer [N_E, 32] -> out [32, N_E].
// Source buffer chosen device-side from *n_hop (0..3).
// ---------------------------------------------------------------------------
__global__ void transpose_out_kernel(const float* __restrict__ b0,
                                     const float* __restrict__ b1,
                                     const float* __restrict__ b2,
                                     const float* __restrict__ b3,
                                     const int* __restrict__ n_hop,
                                     float* __restrict__ out) {
    __shared__ float tile[32][33];
    int nh = *n_hop;
    nh = nh < 0 ? 0 : (nh > 3 ? 3 : nh);
    const float* wt = (nh == 0) ? b0 : (nh == 1) ? b1 : (nh == 2) ? b2 : b3;

    int e0 = blockIdx.x * 32;
    int tx = threadIdx.x, ty = threadIdx.y;
    tile[ty][tx] = wt[(size_t)(e0 + ty) * 32 + tx];
    __syncthreads();
    out[(size_t)ty * N_E + e0 + tx] = tile[tx][ty];
}

// ---------------------------------------------------------------------------
// One hop: for each triple t:  dst[:, obj[t]] += src[:, subj[t]] * r[:, rel[t]]
// Entity-major layout: src/dst are [N_E][32]. Each octet of 8 lanes handles
// TPO=4 consecutive triples; per lane one float4 (4 of the 32 batches).
// Trailing ZERO_BLOCKS (when zbuf != null) zero the NEXT hop's destination,
// overlapping that streaming write with this hop's latency-bound atomics.
// __launch_bounds__(256, 8) caps regs at 32 -> 64 warps/SM for max MLP.
// ---------------------------------------------------------------------------
#define TPO 4   // triples per octet
#define HOP_BLOCKS 15625   // N_T * 8 / TPO / 256

__global__ void __launch_bounds__(256, 8)
hop_kernel(const float* __restrict__ src, float* __restrict__ dst,
           const int* __restrict__ subj, const int* __restrict__ rel,
           const int* __restrict__ obj, const float* __restrict__ rt,
           const int* __restrict__ n_hop, int hop,
           float4* __restrict__ zbuf) {
    if (*n_hop < hop) return;

    int bid = blockIdx.x;
    int tid = threadIdx.x;

    if (bid >= HOP_BLOCKS) {
        // ---- zero next hop's destination (disjoint from dst) ----
        size_t i = (size_t)(bid - HOP_BLOCKS) * 256 + tid;
        zbuf[i] = make_float4(0.f, 0.f, 0.f, 0.f);
        return;
    }

    int lane = tid & 31;
    int sub  = lane & 7;                                    // which float4 of 32 batches
    int oct  = (int)(((size_t)bid * 256 + tid) >> 3);       // octet id
    int t0   = oct * TPO;
    if (t0 >= N_T) return;

    // 4 triples' indices via one int4 load per array (t0 % 4 == 0)
    int4 sA = __ldg(reinterpret_cast<const int4*>(subj + t0));
    int4 rA = __ldg(reinterpret_cast<const int4*>(rel + t0));
    int4 oA = __ldg(reinterpret_cast<const int4*>(obj + t0));

    int s[TPO]  = {sA.x, sA.y, sA.z, sA.w};
    int rl[TPO] = {rA.x, rA.y, rA.z, rA.w};
    int o[TPO]  = {oA.x, oA.y, oA.z, oA.w};

    const float4* src4 = reinterpret_cast<const float4*>(src);
    const float4* rt4  = reinterpret_cast<const float4*>(rt);
    float4* dst4       = reinterpret_cast<float4*>(dst);

    // front-batch all long-latency gathers
    float4 a[TPO];
#pragma unroll
    for (int j = 0; j < TPO; j++) a[j] = __ldg(src4 + (size_t)s[j] * 8 + sub);

    // r-vector loads are hot in L1 (25.6 KB table)
    float4 r4[TPO];
#pragma unroll
    for (int j = 0; j < TPO; j++) r4[j] = __ldg(rt4 + (size_t)rl[j] * 8 + sub);

#pragma unroll
    for (int j = 0; j < TPO; j++) {
        float4 m = make_float4(a[j].x * r4[j].x, a[j].y * r4[j].y,
                               a[j].z * r4[j].z, a[j].w * r4[j].w);
        float4* d = dst4 + (size_t)o[j] * 8 + sub;
        asm volatile("red.global.add.v4.f32 [%0], {%1, %2, %3, %4};"
                     :: "l"(d), "f"(m.x), "f"(m.y), "f"(m.z), "f"(m.w)
                     : "memory");
    }
}

// ---------------------------------------------------------------------------
// kernel_launch
// Input order (metadata): x, q, subj_idx, rel_idx, obj_idx, W1, b1, W2, b2, W3, b3, n_hop
// ---------------------------------------------------------------------------
extern "C" void kernel_launch(void* const* d_in, const int* in_sizes, int n_in,
                              void* d_out, int out_size) {
    const float* x     = (const float*)d_in[0];
    const float* q     = (const float*)d_in[1];
    const int* subj    = (const int*)d_in[2];
    const int* rel     = (const int*)d_in[3];
    const int* obj     = (const int*)d_in[4];
    const float* W1    = (const float*)d_in[5];
    const float* b1    = (const float*)d_in[6];
    const float* W2    = (const float*)d_in[7];
    const float* b2    = (const float*)d_in[8];
    const float* W3    = (const float*)d_in[9];
    const float* b3    = (const float*)d_in[10];
    const int* n_hop   = (const int*)d_in[11];
    float* out         = (float*)d_out;

    float *buf0, *buf1, *buf2, *buf3, *rt;
    cudaGetSymbolAddress((void**)&buf0, g_buf0);
    cudaGetSymbolAddress((void**)&buf1, g_buf1);
    cudaGetSymbolAddress((void**)&buf2, g_buf2);
    cudaGetSymbolAddress((void**)&buf3, g_buf3);
    cudaGetSymbolAddress((void**)&rt, g_rt);

    // prologue: rmlp (first) + zero buf1 + transpose-in, one launch
    fused_pre_kernel<<<PRE_TOTAL_BLOCKS, 256>>>(
        x, q, W1, b1, W2, b2, W3, b3, buf0, (float4*)buf1, rt);

    // hop1 zeroes buf2 alongside; hop2 zeroes buf3; hop3 has no zero section
    hop_kernel<<<HOP_BLOCKS + ZERO_BLOCKS, 256>>>(
        buf0, buf1, subj, rel, obj, rt + 0 * N_R * B_SZ, n_hop, 1, (float4*)buf2);
    hop_kernel<<<HOP_BLOCKS + ZERO_BLOCKS, 256>>>(
        buf1, buf2, subj, rel, obj, rt + 1 * N_R * B_SZ, n_hop, 2, (float4*)buf3);
    hop_kernel<<<HOP_BLOCKS, 256>>>(
        buf2, buf3, subj, rel, obj, rt + 2 * N_R * B_SZ, n_hop, 3, nullptr);

    // back to [B, N_E], selecting the buffer that matches n_hop
    transpose_out_kernel<<<N_E / 32, dim3(32, 32)>>>(buf0, buf1, buf2, buf3, n_hop, out);
}